// round 9
// baseline (speedup 1.0000x reference)
#include <cuda_runtime.h>
#include <math.h>

// x: [2048, 512, 7, 7] fp32.
#define NCH      512
#define HW       49
#define SLAB     (NCH * HW)      // 25088 floats / sample
#define SLAB4    (SLAB / 4)      // 6272 float4 / sample
#define NTHREADS 512
#define NWARPS   (NTHREADS / 32) // 16
#define CH_PER_W (NCH / NWARPS)  // 32 channels per warp
#define EPS      1e-5f

#define STAGE_CH   256                     // channels staged in SMEM
#define STAGE_F    (STAGE_CH * HW)         // 12544 floats (49KB)
#define STAGE_F4   (STAGE_F / 4)           // 3136 float4 (multiple of 32)
// dynamic smem: slab[12544] + ch[513] + red[32]
#define SMEM_FLOATS (STAGE_F + NCH + 1 + 32)
#define SMEM_BYTES  (SMEM_FLOATS * sizeof(float))

__global__ __launch_bounds__(NTHREADS, 4)
void ModelNew_25056839205377_kernel(const float* __restrict__ x,
                                    float* __restrict__ out)
{
    extern __shared__ float sm[];
    float* slab = sm;                  // [STAGE_F]
    float* ch   = sm + STAGE_F;        // [NCH+1]
    float* red  = ch + NCH + 1;        // [32]

    const int tid  = threadIdx.x;
    const int warp = tid >> 5;
    const int lane = tid & 31;
    const size_t base = (size_t)blockIdx.x * SLAB;
    const float* __restrict__ xp = x + base;

    // ---- Phase 1: per-channel mean; warps 0-7 also stage their channels in SMEM.
    #pragma unroll 8
    for (int k = 0; k < CH_PER_W; ++k) {
        const int c = warp * CH_PER_W + k;
        const float* p = xp + c * HW;
        const float v0 = p[lane];
        const float v1 = (lane < HW - 32) ? p[32 + lane] : 0.0f;
        if (c < STAGE_CH) {                       // uniform per warp (warp < 8)
            slab[c * HW + lane] = v0;
            if (lane < HW - 32) slab[c * HW + 32 + lane] = v1;
        }
        float s = v0 + v1;
        #pragma unroll
        for (int o = 16; o > 0; o >>= 1)
            s += __shfl_xor_sync(0xffffffffu, s, o);
        if (lane == 0) ch[c] = s * (1.0f / HW);
    }
    __syncwarp();   // warp w reads back only its own ch[32w..32w+31]

    // ---- Phase 2: warp partials (ch[tid] was written by THIS warp) ----
    const float y = ch[tid];
    float ys = y, y2 = y * y;
    #pragma unroll
    for (int o = 16; o > 0; o >>= 1) {
        ys += __shfl_xor_sync(0xffffffffu, ys, o);
        y2 += __shfl_xor_sync(0xffffffffu, y2, o);
    }
    if (lane == 0) { red[warp] = ys; red[16 + warp] = y2; }
    __syncthreads();                                   // barrier 1

    // ---- Phase 3: redundant final reduce in EVERY warp, then gates ----
    {
        float s1 = (lane < 16) ? red[lane]      : 0.0f;
        float s2 = (lane < 16) ? red[16 + lane] : 0.0f;
        #pragma unroll
        for (int o = 8; o > 0; o >>= 1) {
            s1 += __shfl_xor_sync(0xffffffffu, s1, o);
            s2 += __shfl_xor_sync(0xffffffffu, s2, o);
        }
        s1 = __shfl_sync(0xffffffffu, s1, 0);
        s2 = __shfl_sync(0xffffffffu, s2, 0);
        const float m   = s1 * (1.0f / NCH);
        const float mx2 = s2 * (1.0f / NCH);
        const float var = fmaxf(mx2 - m * m, 0.0f);
        const float inv = rsqrtf(var + EPS);
        const float z   = (y - m) * inv;
        ch[tid] = __expf(-z * z);       // gate, own channel (C_PARAM=2 -> -z^2)
    }
    if (tid == 0) ch[NCH] = 0.0f;
    __syncthreads();                                   // barrier 2

    // ---- Phase 4: first half from SMEM slab, second half from L2 (ldcs) ----
    const float4* __restrict__ x4 = (const float4*)xp;
    const float4* __restrict__ s4 = (const float4*)slab;
    float4* __restrict__ o4 = (float4*)(out + base);

    // A) SMEM part: 3136 float4 = 6*512 + 64
    #pragma unroll
    for (int b = 0; b < 6; ++b) {
        const int i = tid + b * NTHREADS;
        float4 v = s4[i];
        const int e = i * 4;
        const int c = e / HW;
        const int r = e - c * HW;
        const float g0 = ch[c];
        const float gn = ch[c + 1];
        v.x *= g0;
        v.y *= (r < 48) ? g0 : gn;
        v.z *= (r < 47) ? g0 : gn;
        v.w *= (r < 46) ? g0 : gn;
        __stcs(o4 + i, v);
    }
    if (tid < 64) {
        const int i = tid + 6 * NTHREADS;   // 3072..3135
        float4 v = s4[i];
        const int e = i * 4;
        const int c = e / HW;
        const int r = e - c * HW;
        const float g0 = ch[c];
        const float gn = ch[c + 1];
        v.x *= g0;
        v.y *= (r < 48) ? g0 : gn;
        v.z *= (r < 47) ? g0 : gn;
        v.w *= (r < 46) ? g0 : gn;
        __stcs(o4 + i, v);
    }

    // B) GMEM part: indices 3136..6271 (3136 float4 = 4+2 batched + 64 tail)
    #pragma unroll
    for (int b = 0; b < 1; ++b) {   // batch of 4
        const int i0 = STAGE_F4 + tid;
        float4 v0 = __ldcs(x4 + i0 + 0 * NTHREADS);
        float4 v1 = __ldcs(x4 + i0 + 1 * NTHREADS);
        float4 v2 = __ldcs(x4 + i0 + 2 * NTHREADS);
        float4 v3 = __ldcs(x4 + i0 + 3 * NTHREADS);
        #pragma unroll
        for (int k = 0; k < 4; ++k) {
            float4& v = (k == 0) ? v0 : (k == 1) ? v1 : (k == 2) ? v2 : v3;
            const int i = i0 + k * NTHREADS;
            const int e = i * 4;
            const int c = e / HW;
            const int r = e - c * HW;
            const float g0 = ch[c];
            const float gn = ch[c + 1];
            v.x *= g0;
            v.y *= (r < 48) ? g0 : gn;
            v.z *= (r < 47) ? g0 : gn;
            v.w *= (r < 46) ? g0 : gn;
            __stcs(o4 + i, v);
        }
    }
    {   // batch of 2
        const int i0 = STAGE_F4 + 4 * NTHREADS + tid;
        float4 v0 = __ldcs(x4 + i0 + 0 * NTHREADS);
        float4 v1 = __ldcs(x4 + i0 + 1 * NTHREADS);
        #pragma unroll
        for (int k = 0; k < 2; ++k) {
            float4& v = (k == 0) ? v0 : v1;
            const int i = i0 + k * NTHREADS;
            const int e = i * 4;
            const int c = e / HW;
            const int r = e - c * HW;
            const float g0 = ch[c];
            const float gn = ch[c + 1];
            v.x *= g0;
            v.y *= (r < 48) ? g0 : gn;
            v.z *= (r < 47) ? g0 : gn;
            v.w *= (r < 46) ? g0 : gn;
            __stcs(o4 + i, v);
        }
    }
    if (tid < 64) {
        const int i = STAGE_F4 + 6 * NTHREADS + tid;   // 6208..6271
        float4 v = __ldcs(x4 + i);
        const int e = i * 4;
        const int c = e / HW;
        const int r = e - c * HW;
        const float g0 = ch[c];
        const float gn = ch[c + 1];
        v.x *= g0;
        v.y *= (r < 48) ? g0 : gn;
        v.z *= (r < 47) ? g0 : gn;
        v.w *= (r < 46) ? g0 : gn;
        __stcs(o4 + i, v);
    }
}

extern "C" void kernel_launch(void* const* d_in, const int* in_sizes, int n_in,
                              void* d_out, int out_size)
{
    const float* x = (const float*)d_in[0];
    float* out = (float*)d_out;
    const int nblocks = in_sizes[0] / SLAB;   // 2048 samples

    cudaFuncSetAttribute(ModelNew_25056839205377_kernel,
                         cudaFuncAttributeMaxDynamicSharedMemorySize,
                         (int)SMEM_BYTES);

    ModelNew_25056839205377_kernel<<<nblocks, NTHREADS, SMEM_BYTES>>>(x, out);
}

// round 10
// speedup vs baseline: 1.1363x; 1.1363x over previous
#include <cuda_runtime.h>
#include <math.h>

// x: [2048, 512, 7, 7] fp32.
#define NCH      512
#define HW       49
#define SLAB     (NCH * HW)      // 25088 floats / sample
#define SLAB4    (SLAB / 4)      // 6272 float4 / sample
#define NTHREADS 512
#define NWARPS   (NTHREADS / 32) // 16
#define CH_PER_W (NCH / NWARPS)  // 32 channels per warp
#define EPS      1e-5f

// SLAB4 = 512*12 + 128
#define FULL_BATCHES 3
#define REM_THREADS  128

__global__ __launch_bounds__(NTHREADS, 4)
void ModelNew_25056839205377_kernel(const float* __restrict__ x,
                                    float* __restrict__ out)
{
    __shared__ float ch[NCH + 1];   // y[c] -> gate[c]; +1 slack for c+1 read
    __shared__ float red[32];       // 16 sums, 16 sumsqs

    const int tid  = threadIdx.x;
    const int warp = tid >> 5;
    const int lane = tid & 31;
    const size_t base = (size_t)blockIdx.x * SLAB;
    const float* __restrict__ xp = x + base;

    // ---- Phase 1: y[c] = spatial mean. Each warp owns 32 channels. ----
    // __ldcg: cache at L2 (needed for phase-4 re-read), skip L1 allocation.
    #pragma unroll 8
    for (int k = 0; k < CH_PER_W; ++k) {
        const int c = warp * CH_PER_W + k;
        const float* p = xp + c * HW;
        float s = __ldcg(p + lane) +
                  ((lane < HW - 32) ? __ldcg(p + 32 + lane) : 0.0f);
        #pragma unroll
        for (int o = 16; o > 0; o >>= 1)
            s += __shfl_xor_sync(0xffffffffu, s, o);
        if (lane == 0) ch[c] = s * (1.0f / HW);
    }
    __syncwarp();   // warp w reads back only its own ch[32w..32w+31]

    // ---- Phase 2: warp partials over own 32 channels ----
    const float y = ch[tid];
    float ys = y, y2 = y * y;
    #pragma unroll
    for (int o = 16; o > 0; o >>= 1) {
        ys += __shfl_xor_sync(0xffffffffu, ys, o);
        y2 += __shfl_xor_sync(0xffffffffu, y2, o);
    }
    if (lane == 0) { red[warp] = ys; red[16 + warp] = y2; }
    __syncthreads();                                   // barrier 1 of 2

    // ---- Phase 3: redundant final reduce in EVERY warp, then gates ----
    {
        float s1 = (lane < 16) ? red[lane]      : 0.0f;
        float s2 = (lane < 16) ? red[16 + lane] : 0.0f;
        #pragma unroll
        for (int o = 8; o > 0; o >>= 1) {
            s1 += __shfl_xor_sync(0xffffffffu, s1, o);
            s2 += __shfl_xor_sync(0xffffffffu, s2, o);
        }
        s1 = __shfl_sync(0xffffffffu, s1, 0);
        s2 = __shfl_sync(0xffffffffu, s2, 0);
        const float m   = s1 * (1.0f / NCH);
        const float mx2 = s2 * (1.0f / NCH);
        const float var = fmaxf(mx2 - m * m, 0.0f);
        const float inv = rsqrtf(var + EPS);
        const float z   = (y - m) * inv;
        ch[tid] = __expf(-z * z);   // gate (C_PARAM=2 -> -0.5*2*z^2 = -z^2)
    }
    if (tid == 0) ch[NCH] = 0.0f;   // slack slot for predicated c+1 reads
    __syncthreads();                                   // barrier 2 of 2

    // ---- Phase 4: re-read x (L2-hit, evict-first), gate, stream store ----
    const float4* __restrict__ x4 = (const float4*)xp;
    float4* __restrict__ o4 = (float4*)(out + base);

    #pragma unroll
    for (int b = 0; b < FULL_BATCHES; ++b) {
        const int i0 = tid + (4 * b) * NTHREADS;
        // 4 independent 128b loads in flight before any store
        float4 v0 = __ldcs(x4 + i0 + 0 * NTHREADS);
        float4 v1 = __ldcs(x4 + i0 + 1 * NTHREADS);
        float4 v2 = __ldcs(x4 + i0 + 2 * NTHREADS);
        float4 v3 = __ldcs(x4 + i0 + 3 * NTHREADS);
        #pragma unroll
        for (int k = 0; k < 4; ++k) {
            float4& v = (k == 0) ? v0 : (k == 1) ? v1 : (k == 2) ? v2 : v3;
            const int e = (i0 + k * NTHREADS) * 4;
            const int c = e / HW;            // constant div -> mul+shift
            const int r = e - c * HW;        // 0..48
            const float g0 = ch[c];
            const float gn = ch[c + 1];
            v.x *= g0;
            v.y *= (r < 48) ? g0 : gn;
            v.z *= (r < 47) ? g0 : gn;
            v.w *= (r < 46) ? g0 : gn;
            __stcs(o4 + i0 + k * NTHREADS, v);
        }
    }
    // remainder: SLAB4 - 12*512 = 128 float4s
    if (tid < REM_THREADS) {
        const int i = tid + 12 * NTHREADS;
        float4 v = __ldcs(x4 + i);
        const int e = i * 4;
        const int c = e / HW;
        const int r = e - c * HW;
        const float g0 = ch[c];
        const float gn = ch[c + 1];
        v.x *= g0;
        v.y *= (r < 48) ? g0 : gn;
        v.z *= (r < 47) ? g0 : gn;
        v.w *= (r < 46) ? g0 : gn;
        __stcs(o4 + i, v);
    }
}

extern "C" void kernel_launch(void* const* d_in, const int* in_sizes, int n_in,
                              void* d_out, int out_size)
{
    const float* x = (const float*)d_in[0];
    float* out = (float*)d_out;
    const int nblocks = in_sizes[0] / SLAB;   // 2048 samples
    ModelNew_25056839205377_kernel<<<nblocks, NTHREADS>>>(x, out);
}

// round 12
// speedup vs baseline: 1.1730x; 1.0322x over previous
#include <cuda_runtime.h>
#include <math.h>

// x: [2048, 512, 7, 7] fp32.
#define NCH      512
#define HW       49
#define SLAB     (NCH * HW)      // 25088 floats / sample
#define SLAB4    (SLAB / 4)      // 6272 float4 / sample
#define NTHREADS 512
#define NWARPS   (NTHREADS / 32) // 16
#define CH_PER_W (NCH / NWARPS)  // 32 channels per warp
#define EPS      1e-5f

// SLAB4 = 512*12 + 128
#define FULL_BATCHES 3
#define REM_THREADS  128

__global__ __launch_bounds__(NTHREADS, 4)
void ModelNew_25056839205377_kernel(const float* __restrict__ x,
                                    float* __restrict__ out)
{
    __shared__ float ch[NCH + 1];   // y[c] -> gate[c]; +1 slack for c+1 read
    __shared__ float red[32];       // 16 sums, 16 sumsqs

    const int tid  = threadIdx.x;
    const int warp = tid >> 5;
    const int lane = tid & 31;
    const size_t base = (size_t)blockIdx.x * SLAB;
    const float* __restrict__ xp = x + base;

    // ---- Phase 1: y[c] = spatial mean. Each warp owns 32 channels. ----
    // Default caching loads (L1+L2): adjacent channels share lines -> L1 hits,
    // and lines stay in L2 for the phase-4 re-read.
    #pragma unroll 8
    for (int k = 0; k < CH_PER_W; ++k) {
        const int c = warp * CH_PER_W + k;
        const float* p = xp + c * HW;
        float s = p[lane] + ((lane < HW - 32) ? p[32 + lane] : 0.0f);
        #pragma unroll
        for (int o = 16; o > 0; o >>= 1)
            s += __shfl_xor_sync(0xffffffffu, s, o);
        if (lane == 0) ch[c] = s * (1.0f / HW);
    }
    __syncwarp();   // warp w reads back only its own ch[32w..32w+31]

    // ---- Phase 2: warp partials over own 32 channels ----
    const float y = ch[tid];
    float ys = y, y2 = y * y;
    #pragma unroll
    for (int o = 16; o > 0; o >>= 1) {
        ys += __shfl_xor_sync(0xffffffffu, ys, o);
        y2 += __shfl_xor_sync(0xffffffffu, y2, o);
    }
    if (lane == 0) { red[warp] = ys; red[16 + warp] = y2; }
    __syncthreads();                                   // barrier 1 of 2

    // ---- Phase 3: redundant final reduce in EVERY warp, then gates ----
    {
        float s1 = (lane < 16) ? red[lane]      : 0.0f;
        float s2 = (lane < 16) ? red[16 + lane] : 0.0f;
        #pragma unroll
        for (int o = 8; o > 0; o >>= 1) {
            s1 += __shfl_xor_sync(0xffffffffu, s1, o);
            s2 += __shfl_xor_sync(0xffffffffu, s2, o);
        }
        s1 = __shfl_sync(0xffffffffu, s1, 0);
        s2 = __shfl_sync(0xffffffffu, s2, 0);
        const float m   = s1 * (1.0f / NCH);
        const float mx2 = s2 * (1.0f / NCH);
        const float var = fmaxf(mx2 - m * m, 0.0f);
        const float inv = rsqrtf(var + EPS);
        const float z   = (y - m) * inv;
        ch[tid] = __expf(-z * z);   // gate (C_PARAM=2 -> -0.5*2*z^2 = -z^2)
    }
    if (tid == 0) ch[NCH] = 0.0f;   // slack slot for predicated c+1 reads
    __syncthreads();                                   // barrier 2 of 2

    // ---- Phase 4: re-read x (L2-hit, evict-first), gate, stream store ----
    const float4* __restrict__ x4 = (const float4*)xp;
    float4* __restrict__ o4 = (float4*)(out + base);

    #pragma unroll
    for (int b = 0; b < FULL_BATCHES; ++b) {
        const int i0 = tid + (4 * b) * NTHREADS;
        // 4 independent 128b loads in flight before any store
        float4 v0 = __ldcs(x4 + i0 + 0 * NTHREADS);
        float4 v1 = __ldcs(x4 + i0 + 1 * NTHREADS);
        float4 v2 = __ldcs(x4 + i0 + 2 * NTHREADS);
        float4 v3 = __ldcs(x4 + i0 + 3 * NTHREADS);
        #pragma unroll
        for (int k = 0; k < 4; ++k) {
            float4& v = (k == 0) ? v0 : (k == 1) ? v1 : (k == 2) ? v2 : v3;
            const int e = (i0 + k * NTHREADS) * 4;
            const int c = e / HW;            // constant div -> mul+shift
            const int r = e - c * HW;        // 0..48
            const float g0 = ch[c];
            const float gn = ch[c + 1];
            v.x *= g0;
            v.y *= (r < 48) ? g0 : gn;
            v.z *= (r < 47) ? g0 : gn;
            v.w *= (r < 46) ? g0 : gn;
            __stcs(o4 + i0 + k * NTHREADS, v);
        }
    }
    // remainder: SLAB4 - 12*512 = 128 float4s
    if (tid < REM_THREADS) {
        const int i = tid + 12 * NTHREADS;
        float4 v = __ldcs(x4 + i);
        const int e = i * 4;
        const int c = e / HW;
        const int r = e - c * HW;
        const float g0 = ch[c];
        const float gn = ch[c + 1];
        v.x *= g0;
        v.y *= (r < 48) ? g0 : gn;
        v.z *= (r < 47) ? g0 : gn;
        v.w *= (r < 46) ? g0 : gn;
        __stcs(o4 + i, v);
    }
}

extern "C" void kernel_launch(void* const* d_in, const int* in_sizes, int n_in,
                              void* d_out, int out_size)
{
    const float* x = (const float*)d_in[0];
    float* out = (float*)d_out;
    const int nblocks = in_sizes[0] / SLAB;   // 2048 samples
    ModelNew_25056839205377_kernel<<<nblocks, NTHREADS>>>(x, out);
}